// round 3
// baseline (speedup 1.0000x reference)
#include <cuda_runtime.h>
#include <math.h>

#define B 16384
#define D 2048
#define E 16
#define C 64

// Scratch (no allocations allowed): routing buckets + counts.
__device__ int g_counts[E];
__device__ int g_bucket[E * B];

__global__ void zero_counts_kernel() {
    if (threadIdx.x < E) g_counts[threadIdx.x] = 0;
}

// ---------------------------------------------------------------------------
// Kernel 1: coarse router GEMM [B,16] + bias + argmax + bucket scatter.
// Block tile: 128 samples x 16 experts, 256 threads.
// Thread tile: 4 samples x 2 experts. Per kk: 1 LDS.128 + 2 LDS.32, 8 FFMA.
// ---------------------------------------------------------------------------
#define C1_TM 128
#define C1_TK 32
#define C1_FS (C1_TM + 4)
#define C1_WS (E + 4)

__global__ __launch_bounds__(256) void coarse_kernel(
    const float* __restrict__ features,
    const float* __restrict__ cw,
    const float* __restrict__ cb,
    float* __restrict__ out_coarse,
    float* __restrict__ out_eid)
{
    __shared__ __align__(16) float fs[C1_TK][C1_FS];  // [k][sample]
    __shared__ __align__(16) float ws[C1_TK][C1_WS];  // [k][expert]

    int tid = threadIdx.x;
    int s0  = blockIdx.x * C1_TM;
    int ty  = tid >> 3;   // 0..31 -> samples ty*4..ty*4+3
    int tx  = tid & 7;    // experts tx and tx+8

    float acc0[4] = {0.f, 0.f, 0.f, 0.f};
    float acc1[4] = {0.f, 0.f, 0.f, 0.f};

    for (int k0 = 0; k0 < D; k0 += C1_TK) {
        // stage features: 128 samples x 32 k = 1024 float4, 4/thread, transposed
        #pragma unroll
        for (int it = 0; it < 4; it++) {
            int task = tid + it * 256;
            int s  = task >> 3;
            int kc = task & 7;
            float4 v = *(const float4*)(features + (size_t)(s0 + s) * D + k0 + kc * 4);
            fs[kc * 4 + 0][s] = v.x;
            fs[kc * 4 + 1][s] = v.y;
            fs[kc * 4 + 2][s] = v.z;
            fs[kc * 4 + 3][s] = v.w;
        }
        // stage coarse weights: 16 experts x 32 k = 128 float4
        if (tid < 128) {
            int we = tid >> 3;
            int kc = tid & 7;
            float4 w = *(const float4*)(cw + (size_t)we * D + k0 + kc * 4);
            ws[kc * 4 + 0][we] = w.x;
            ws[kc * 4 + 1][we] = w.y;
            ws[kc * 4 + 2][we] = w.z;
            ws[kc * 4 + 3][we] = w.w;
        }
        __syncthreads();

        #pragma unroll
        for (int kk = 0; kk < C1_TK; kk++) {
            float4 fa = *(const float4*)&fs[kk][ty * 4];
            float w0 = ws[kk][tx];
            float w1 = ws[kk][tx + 8];
            float f[4] = {fa.x, fa.y, fa.z, fa.w};
            #pragma unroll
            for (int i = 0; i < 4; i++) {
                acc0[i] = fmaf(f[i], w0, acc0[i]);
                acc1[i] = fmaf(f[i], w1, acc1[i]);
            }
        }
        __syncthreads();
    }

    float b0 = cb[tx];
    float b1 = cb[tx + 8];
    #pragma unroll
    for (int i = 0; i < 4; i++) {
        float v0 = acc0[i] + b0;
        float v1 = acc1[i] + b1;
        int gs = s0 + ty * 4 + i;
        out_coarse[(size_t)gs * E + tx]     = v0;
        out_coarse[(size_t)gs * E + tx + 8] = v1;

        // first-occurrence argmax over 16 experts (8 lanes x 2 candidates)
        float mv = v0; int mi = tx;
        if (v1 > mv) { mv = v1; mi = tx + 8; }
        #pragma unroll
        for (int off = 1; off < 8; off <<= 1) {
            float ov = __shfl_xor_sync(0xffffffffu, mv, off);
            int   oi = __shfl_xor_sync(0xffffffffu, mi, off);
            if (ov > mv || (ov == mv && oi < mi)) { mv = ov; mi = oi; }
        }
        if (tx == 0) {
            out_eid[gs] = (float)mi;
            int pos = atomicAdd(&g_counts[mi], 1);
            g_bucket[mi * B + pos] = gs;
        }
    }
}

// ---------------------------------------------------------------------------
// Kernel 2: per-expert gathered GEMM [cnt_e, 64] + bias + softmax + argmax.
// Block tile: 64 samples x 64 classes, 128 threads.
// Thread tile: 4 samples x 8 classes. Per kk: 3 LDS.128, 32 FFMA.
// Epilogue fully in registers + shfl (classes of a sample = 8 adjacent lanes).
// ---------------------------------------------------------------------------
#define K2_TM 64
#define K2_TK 32
#define K2_FS (K2_TM + 4)
#define K2_WS (C + 8)

__global__ __launch_bounds__(128) void expert_kernel(
    const float* __restrict__ features,
    const float* __restrict__ ew,
    const float* __restrict__ eb,
    float* __restrict__ out_local,
    float* __restrict__ out_global)
{
    __shared__ __align__(16) float fs[K2_TK][K2_FS];  // [k][sample]
    __shared__ __align__(16) float ws[K2_TK][K2_WS];  // [k][class]
    __shared__ int ridx[K2_TM];

    int e   = blockIdx.y;
    int cnt = g_counts[e];
    int m0  = blockIdx.x * K2_TM;
    if (m0 >= cnt) return;

    int tid = threadIdx.x;
    if (tid < K2_TM) {
        int r = m0 + tid;
        ridx[tid] = (r < cnt) ? g_bucket[e * B + r] : -1;
    }
    __syncthreads();

    int ty = tid >> 3;   // 0..15 -> samples ty*4..ty*4+3
    int tx = tid & 7;    // classes tx*8..tx*8+7
    const float* wbase = ew + (size_t)e * C * D;

    float acc[4][8];
    #pragma unroll
    for (int i = 0; i < 4; i++)
        #pragma unroll
        for (int j = 0; j < 8; j++)
            acc[i][j] = 0.f;

    for (int k0 = 0; k0 < D; k0 += K2_TK) {
        // stage gathered features: 64 samples x 32 k = 512 float4, 4/thread
        #pragma unroll
        for (int it = 0; it < 4; it++) {
            int task = tid + it * 128;
            int s  = task >> 3;
            int kc = task & 7;
            int row = ridx[s];
            float4 v = make_float4(0.f, 0.f, 0.f, 0.f);
            if (row >= 0)
                v = *(const float4*)(features + (size_t)row * D + k0 + kc * 4);
            fs[kc * 4 + 0][s] = v.x;
            fs[kc * 4 + 1][s] = v.y;
            fs[kc * 4 + 2][s] = v.z;
            fs[kc * 4 + 3][s] = v.w;
        }
        // stage expert weights: 64 classes x 32 k = 512 float4, 4/thread
        #pragma unroll
        for (int it = 0; it < 4; it++) {
            int task = tid + it * 128;
            int c  = task >> 3;
            int kc = task & 7;
            float4 w = *(const float4*)(wbase + (size_t)c * D + k0 + kc * 4);
            ws[kc * 4 + 0][c] = w.x;
            ws[kc * 4 + 1][c] = w.y;
            ws[kc * 4 + 2][c] = w.z;
            ws[kc * 4 + 3][c] = w.w;
        }
        __syncthreads();

        #pragma unroll
        for (int kk = 0; kk < K2_TK; kk++) {
            float4 fa  = *(const float4*)&fs[kk][ty * 4];
            float4 wb0 = *(const float4*)&ws[kk][tx * 8];
            float4 wb1 = *(const float4*)&ws[kk][tx * 8 + 4];
            float f[4] = {fa.x, fa.y, fa.z, fa.w};
            float w[8] = {wb0.x, wb0.y, wb0.z, wb0.w, wb1.x, wb1.y, wb1.z, wb1.w};
            #pragma unroll
            for (int i = 0; i < 4; i++)
                #pragma unroll
                for (int j = 0; j < 8; j++)
                    acc[i][j] = fmaf(f[i], w[j], acc[i][j]);
        }
        __syncthreads();
    }

    // epilogue: bias + row softmax + first-occurrence argmax, all in regs/shfl
    float bias[8];
    {
        float4 b0 = *(const float4*)(eb + e * C + tx * 8);
        float4 b1 = *(const float4*)(eb + e * C + tx * 8 + 4);
        bias[0] = b0.x; bias[1] = b0.y; bias[2] = b0.z; bias[3] = b0.w;
        bias[4] = b1.x; bias[5] = b1.y; bias[6] = b1.z; bias[7] = b1.w;
    }

    #pragma unroll
    for (int i = 0; i < 4; i++) {
        float v[8];
        #pragma unroll
        for (int j = 0; j < 8; j++) v[j] = acc[i][j] + bias[j];

        // local first-occurrence argmax
        float mv = v[0]; int mi = tx * 8;
        #pragma unroll
        for (int j = 1; j < 8; j++)
            if (v[j] > mv) { mv = v[j]; mi = tx * 8 + j; }
        // combine across the 8 lanes holding this sample's 64 classes
        #pragma unroll
        for (int off = 1; off < 8; off <<= 1) {
            float ov = __shfl_xor_sync(0xffffffffu, mv, off);
            int   oi = __shfl_xor_sync(0xffffffffu, mi, off);
            if (ov > mv || (ov == mv && oi < mi)) { mv = ov; mi = oi; }
        }

        float sum = 0.f;
        #pragma unroll
        for (int j = 0; j < 8; j++) {
            v[j] = expf(v[j] - mv);
            sum += v[j];
        }
        #pragma unroll
        for (int off = 1; off < 8; off <<= 1)
            sum += __shfl_xor_sync(0xffffffffu, sum, off);
        float inv = 1.0f / sum;

        int sm  = ty * 4 + i;
        int row = ridx[sm];
        if (row >= 0) {
            float4 o0 = make_float4(v[0] * inv, v[1] * inv, v[2] * inv, v[3] * inv);
            float4 o1 = make_float4(v[4] * inv, v[5] * inv, v[6] * inv, v[7] * inv);
            *(float4*)(out_local + (size_t)row * C + tx * 8)     = o0;
            *(float4*)(out_local + (size_t)row * C + tx * 8 + 4) = o1;
            if (tx == 0)
                out_global[row] = (float)(mi + e * C);
        }
    }
}

// ---------------------------------------------------------------------------
// Output layout (reference tuple order, flattened+concatenated, fp32):
//   [0,              B*E)              coarse_output
//   [B*E,            B*E+B)            expert_id (as float)
//   [B*E+B,          B*E+B+B*C)        local_preds
//   [B*E+B+B*C,      B*E+2B+B*C)       global_preds
// ---------------------------------------------------------------------------
extern "C" void kernel_launch(void* const* d_in, const int* in_sizes, int n_in,
                              void* d_out, int out_size) {
    const float* features = (const float*)d_in[0];
    const float* cw       = (const float*)d_in[1];
    const float* cb       = (const float*)d_in[2];
    const float* ew       = (const float*)d_in[3];
    const float* eb       = (const float*)d_in[4];

    float* out        = (float*)d_out;
    float* out_coarse = out;
    float* out_eid    = out + (size_t)B * E;
    float* out_local  = out_eid + B;
    float* out_global = out_local + (size_t)B * C;

    zero_counts_kernel<<<1, 32>>>();
    coarse_kernel<<<B / C1_TM, 256>>>(features, cw, cb, out_coarse, out_eid);
    dim3 g2(B / K2_TM, E);   // x = m-tile (worst case), y = expert
    expert_kernel<<<g2, 128>>>(features, ew, eb, out_local, out_global);
}

// round 5
// speedup vs baseline: 2.1874x; 2.1874x over previous
#include <cuda_runtime.h>
#include <math.h>

#define B 16384
#define D 2048
#define E 16
#define C 64

// Scratch (no allocations allowed): routing buckets + counts.
__device__ int g_counts[E];
__device__ int g_bucket[E * B];

__global__ void zero_counts_kernel() {
    if (threadIdx.x < E) g_counts[threadIdx.x] = 0;
}

// ---------------------------------------------------------------------------
// Kernel 1: coarse router GEMM [B,16] + bias + argmax + bucket scatter.
// Block tile: 128 samples x 16 experts, 256 threads, double-buffered staging.
// Thread tile: 4 samples x 2 experts.
// ---------------------------------------------------------------------------
#define C1_TM 128
#define C1_TK 32
#define C1_FS (C1_TM + 4)
#define C1_WS (E + 4)
#define NCHUNK (D / C1_TK)

__global__ __launch_bounds__(256) void coarse_kernel(
    const float* __restrict__ features,
    const float* __restrict__ cw,
    const float* __restrict__ cb,
    float* __restrict__ out_coarse,
    float* __restrict__ out_eid)
{
    __shared__ __align__(16) float fs[2][C1_TK][C1_FS];  // [buf][k][sample]
    __shared__ __align__(16) float ws[2][C1_TK][C1_WS];  // [buf][k][expert]

    int tid = threadIdx.x;
    int s0  = blockIdx.x * C1_TM;
    int ty  = tid >> 3;   // 0..31 -> samples ty*4..ty*4+3
    int tx  = tid & 7;    // experts tx and tx+8

    // staging thread mapping
    int st_s  = tid >> 3;      // 0..31 base sample (fs tasks add it*32)
    int st_kc = tid & 7;       // float4 column within chunk
    int w_e   = tid >> 3;      // weight expert (tid<128)
    int w_kc  = tid & 7;

    float4 pf[4];   // prefetched features (4 tasks)
    float4 pw;      // prefetched weights (tid<128)

    float acc0[4] = {0.f, 0.f, 0.f, 0.f};
    float acc1[4] = {0.f, 0.f, 0.f, 0.f};

    // --- prologue: load chunk 0 ---
    {
        int k0 = 0;
        #pragma unroll
        for (int it = 0; it < 4; it++)
            pf[it] = *(const float4*)(features + (size_t)(s0 + st_s + it * 32) * D + k0 + st_kc * 4);
        if (tid < 128)
            pw = *(const float4*)(cw + (size_t)w_e * D + k0 + w_kc * 4);
    }
    // store chunk 0 into buf 0
    #pragma unroll
    for (int it = 0; it < 4; it++) {
        int s = st_s + it * 32;
        fs[0][st_kc * 4 + 0][s] = pf[it].x;
        fs[0][st_kc * 4 + 1][s] = pf[it].y;
        fs[0][st_kc * 4 + 2][s] = pf[it].z;
        fs[0][st_kc * 4 + 3][s] = pf[it].w;
    }
    if (tid < 128) {
        ws[0][w_kc * 4 + 0][w_e] = pw.x;
        ws[0][w_kc * 4 + 1][w_e] = pw.y;
        ws[0][w_kc * 4 + 2][w_e] = pw.z;
        ws[0][w_kc * 4 + 3][w_e] = pw.w;
    }
    __syncthreads();

    for (int chunk = 0; chunk < NCHUNK; chunk++) {
        int cur = chunk & 1;
        int nxt = cur ^ 1;
        if (chunk + 1 < NCHUNK) {
            int k0 = (chunk + 1) * C1_TK;
            #pragma unroll
            for (int it = 0; it < 4; it++)
                pf[it] = *(const float4*)(features + (size_t)(s0 + st_s + it * 32) * D + k0 + st_kc * 4);
            if (tid < 128)
                pw = *(const float4*)(cw + (size_t)w_e * D + k0 + w_kc * 4);
        }

        #pragma unroll
        for (int kk = 0; kk < C1_TK; kk++) {
            float4 fa = *(const float4*)&fs[cur][kk][ty * 4];
            float w0 = ws[cur][kk][tx];
            float w1 = ws[cur][kk][tx + 8];
            float f[4] = {fa.x, fa.y, fa.z, fa.w};
            #pragma unroll
            for (int i = 0; i < 4; i++) {
                acc0[i] = fmaf(f[i], w0, acc0[i]);
                acc1[i] = fmaf(f[i], w1, acc1[i]);
            }
        }

        if (chunk + 1 < NCHUNK) {
            #pragma unroll
            for (int it = 0; it < 4; it++) {
                int s = st_s + it * 32;
                fs[nxt][st_kc * 4 + 0][s] = pf[it].x;
                fs[nxt][st_kc * 4 + 1][s] = pf[it].y;
                fs[nxt][st_kc * 4 + 2][s] = pf[it].z;
                fs[nxt][st_kc * 4 + 3][s] = pf[it].w;
            }
            if (tid < 128) {
                ws[nxt][w_kc * 4 + 0][w_e] = pw.x;
                ws[nxt][w_kc * 4 + 1][w_e] = pw.y;
                ws[nxt][w_kc * 4 + 2][w_e] = pw.z;
                ws[nxt][w_kc * 4 + 3][w_e] = pw.w;
            }
            __syncthreads();
        }
    }

    float b0 = cb[tx];
    float b1 = cb[tx + 8];
    #pragma unroll
    for (int i = 0; i < 4; i++) {
        float v0 = acc0[i] + b0;
        float v1 = acc1[i] + b1;
        int gs = s0 + ty * 4 + i;
        out_coarse[(size_t)gs * E + tx]     = v0;
        out_coarse[(size_t)gs * E + tx + 8] = v1;

        // first-occurrence argmax over 16 experts (8 lanes x 2 candidates)
        float mv = v0; int mi = tx;
        if (v1 > mv) { mv = v1; mi = tx + 8; }
        #pragma unroll
        for (int off = 1; off < 8; off <<= 1) {
            float ov = __shfl_xor_sync(0xffffffffu, mv, off);
            int   oi = __shfl_xor_sync(0xffffffffu, mi, off);
            if (ov > mv || (ov == mv && oi < mi)) { mv = ov; mi = oi; }
        }
        if (tx == 0) {
            out_eid[gs] = (float)mi;
            int pos = atomicAdd(&g_counts[mi], 1);
            g_bucket[mi * B + pos] = gs;
        }
    }
}

// ---------------------------------------------------------------------------
// Kernel 2: per-expert gathered GEMM [cnt_e, 64] + bias + softmax + argmax.
// Block tile: 64 samples x 64 classes, 256 threads, double-buffered staging.
// Thread tile: 4 samples x 4 classes. Epilogue in registers + 16-lane shfl.
// ---------------------------------------------------------------------------
#define K2_TM 64
#define K2_TK 32
#define K2_FS (K2_TM + 4)
#define K2_WS (C + 8)

__global__ __launch_bounds__(256) void expert_kernel(
    const float* __restrict__ features,
    const float* __restrict__ ew,
    const float* __restrict__ eb,
    float* __restrict__ out_local,
    float* __restrict__ out_global)
{
    __shared__ __align__(16) float fs[2][K2_TK][K2_FS];  // [buf][k][sample]
    __shared__ __align__(16) float ws[2][K2_TK][K2_WS];  // [buf][k][class]
    __shared__ int ridx[K2_TM];

    int e   = blockIdx.x;
    int cnt = g_counts[e];
    int m0  = blockIdx.y * K2_TM;
    if (m0 >= cnt) return;

    int tid = threadIdx.x;
    if (tid < K2_TM) {
        int r = m0 + tid;
        ridx[tid] = (r < cnt) ? g_bucket[e * B + r] : -1;
    }
    __syncthreads();

    int ty = tid >> 4;   // 0..15 -> samples ty*4..ty*4+3
    int tx = tid & 15;   // classes tx*4..tx*4+3
    const float* wbase = ew + (size_t)e * C * D;

    // staging mapping: 512 float4 per tile, 2 tasks/thread
    int st_r  = tid >> 3;     // 0..31 base row (tasks add it*32)
    int st_kc = tid & 7;
    int frow0 = ridx[st_r];
    int frow1 = ridx[st_r + 32];

    float4 pf[2], pw[2];

    float acc[4][4];
    #pragma unroll
    for (int i = 0; i < 4; i++)
        #pragma unroll
        for (int j = 0; j < 4; j++)
            acc[i][j] = 0.f;

    // --- prologue: load chunk 0 ---
    pf[0] = (frow0 >= 0) ? *(const float4*)(features + (size_t)frow0 * D + st_kc * 4)
                         : make_float4(0.f, 0.f, 0.f, 0.f);
    pf[1] = (frow1 >= 0) ? *(const float4*)(features + (size_t)frow1 * D + st_kc * 4)
                         : make_float4(0.f, 0.f, 0.f, 0.f);
    pw[0] = *(const float4*)(wbase + (size_t)st_r * D + st_kc * 4);
    pw[1] = *(const float4*)(wbase + (size_t)(st_r + 32) * D + st_kc * 4);

    #pragma unroll
    for (int it = 0; it < 2; it++) {
        int s = st_r + it * 32;
        fs[0][st_kc * 4 + 0][s] = pf[it].x;
        fs[0][st_kc * 4 + 1][s] = pf[it].y;
        fs[0][st_kc * 4 + 2][s] = pf[it].z;
        fs[0][st_kc * 4 + 3][s] = pf[it].w;
        ws[0][st_kc * 4 + 0][s] = pw[it].x;
        ws[0][st_kc * 4 + 1][s] = pw[it].y;
        ws[0][st_kc * 4 + 2][s] = pw[it].z;
        ws[0][st_kc * 4 + 3][s] = pw[it].w;
    }
    __syncthreads();

    const int NCH = D / K2_TK;
    for (int chunk = 0; chunk < NCH; chunk++) {
        int cur = chunk & 1;
        int nxt = cur ^ 1;
        if (chunk + 1 < NCH) {
            int k0 = (chunk + 1) * K2_TK;
            pf[0] = (frow0 >= 0) ? *(const float4*)(features + (size_t)frow0 * D + k0 + st_kc * 4)
                                 : make_float4(0.f, 0.f, 0.f, 0.f);
            pf[1] = (frow1 >= 0) ? *(const float4*)(features + (size_t)frow1 * D + k0 + st_kc * 4)
                                 : make_float4(0.f, 0.f, 0.f, 0.f);
            pw[0] = *(const float4*)(wbase + (size_t)st_r * D + k0 + st_kc * 4);
            pw[1] = *(const float4*)(wbase + (size_t)(st_r + 32) * D + k0 + st_kc * 4);
        }

        #pragma unroll
        for (int kk = 0; kk < K2_TK; kk++) {
            float4 fa = *(const float4*)&fs[cur][kk][ty * 4];
            float4 wb = *(const float4*)&ws[cur][kk][tx * 4];
            float f[4] = {fa.x, fa.y, fa.z, fa.w};
            float w[4] = {wb.x, wb.y, wb.z, wb.w};
            #pragma unroll
            for (int i = 0; i < 4; i++)
                #pragma unroll
                for (int j = 0; j < 4; j++)
                    acc[i][j] = fmaf(f[i], w[j], acc[i][j]);
        }

        if (chunk + 1 < NCH) {
            #pragma unroll
            for (int it = 0; it < 2; it++) {
                int s = st_r + it * 32;
                fs[nxt][st_kc * 4 + 0][s] = pf[it].x;
                fs[nxt][st_kc * 4 + 1][s] = pf[it].y;
                fs[nxt][st_kc * 4 + 2][s] = pf[it].z;
                fs[nxt][st_kc * 4 + 3][s] = pf[it].w;
                ws[nxt][st_kc * 4 + 0][s] = pw[it].x;
                ws[nxt][st_kc * 4 + 1][s] = pw[it].y;
                ws[nxt][st_kc * 4 + 2][s] = pw[it].z;
                ws[nxt][st_kc * 4 + 3][s] = pw[it].w;
            }
            __syncthreads();
        }
    }

    // epilogue: bias + softmax + first-occurrence argmax in regs + 16-lane shfl
    float4 b4 = *(const float4*)(eb + e * C + tx * 4);
    float bias[4] = {b4.x, b4.y, b4.z, b4.w};

    #pragma unroll
    for (int i = 0; i < 4; i++) {
        float v[4];
        #pragma unroll
        for (int j = 0; j < 4; j++) v[j] = acc[i][j] + bias[j];

        float mv = v[0]; int mi = tx * 4;
        #pragma unroll
        for (int j = 1; j < 4; j++)
            if (v[j] > mv) { mv = v[j]; mi = tx * 4 + j; }
        // combine across the 16 lanes holding this sample's 64 classes
        #pragma unroll
        for (int off = 1; off < 16; off <<= 1) {
            float ov = __shfl_xor_sync(0xffffffffu, mv, off);
            int   oi = __shfl_xor_sync(0xffffffffu, mi, off);
            if (ov > mv || (ov == mv && oi < mi)) { mv = ov; mi = oi; }
        }

        float sum = 0.f;
        #pragma unroll
        for (int j = 0; j < 4; j++) {
            v[j] = expf(v[j] - mv);
            sum += v[j];
        }
        #pragma unroll
        for (int off = 1; off < 16; off <<= 1)
            sum += __shfl_xor_sync(0xffffffffu, sum, off);
        float inv = 1.0f / sum;

        int sm  = ty * 4 + i;
        int row = ridx[sm];
        if (row >= 0) {
            float4 o = make_float4(v[0] * inv, v[1] * inv, v[2] * inv, v[3] * inv);
            *(float4*)(out_local + (size_t)row * C + tx * 4) = o;
            if (tx == 0)
                out_global[row] = (float)(mi + e * C);
        }
    }
}

// ---------------------------------------------------------------------------
// Output layout (reference tuple order, flattened+concatenated, fp32):
//   [0,              B*E)              coarse_output
//   [B*E,            B*E+B)            expert_id (as float)
//   [B*E+B,          B*E+B+B*C)        local_preds
//   [B*E+B+B*C,      B*E+2B+B*C)       global_preds
// ---------------------------------------------------------------------------
extern "C" void kernel_launch(void* const* d_in, const int* in_sizes, int n_in,
                              void* d_out, int out_size) {
    const float* features = (const float*)d_in[0];
    const float* cw       = (const float*)d_in[1];
    const float* cb       = (const float*)d_in[2];
    const float* ew       = (const float*)d_in[3];
    const float* eb       = (const float*)d_in[4];

    float* out        = (float*)d_out;
    float* out_coarse = out;
    float* out_eid    = out + (size_t)B * E;
    float* out_local  = out_eid + B;
    float* out_global = out_local + (size_t)B * C;

    zero_counts_kernel<<<1, 32>>>();
    coarse_kernel<<<B / C1_TM, 256>>>(features, cw, cb, out_coarse, out_eid);
    dim3 g2(E, B / K2_TM);   // x = expert (fastest) -> wave 1 all-working
    expert_kernel<<<g2, 256>>>(features, ew, eb, out_local, out_global);
}